// round 9
// baseline (speedup 1.0000x reference)
#include <cuda_runtime.h>

#define KC 32
#define LC 64
#define HC 256
#define OC 32
#define BMAX 256
#define NMAX 100000
#define CPG 4
#define TNODES 4                 // nodes per warp tile
#define CHUNK (8 * TNODES)       // 32 nodes per CTA chunk

#define ZW1_SMEM ((LC*HC + 4*LC) * 4)
// zw1s + w2p + ss + hsm + b1s + b2s (floats) + nids (ints)
#define MAIN_FLOATS (KC*HC + HC*OC + CHUNK*KC + 8*TNODES*HC + HC + OC)
#define MAIN_SMEM (MAIN_FLOATS * 4 + CHUNK * 4)

// ---------------- f32x2 packed-pair helpers (Blackwell FFMA2) -------------
typedef unsigned long long u64;

__device__ __forceinline__ u64 fma2(u64 a, u64 b, u64 c) {
    u64 d;
    asm("fma.rn.f32x2 %0, %1, %2, %3;" : "=l"(d) : "l"(a), "l"(b), "l"(c));
    return d;
}
__device__ __forceinline__ u64 pack2(float lo, float hi) {
    u64 d;
    asm("mov.b64 %0, {%1, %2};" : "=l"(d) : "f"(lo), "f"(hi));
    return d;
}
__device__ __forceinline__ void unpack2(u64 v, float& lo, float& hi) {
    asm("mov.b64 {%0, %1}, %2;" : "=f"(lo), "=f"(hi) : "l"(v));
}

// ---------------- device scratch (no allocations allowed) ----------------
__device__ float g_zw1[BMAX * KC * HC];   // 8 MB: z @ W1 per (graph, cluster)
__device__ int   g_perm[NMAX];            // node ids sorted by graph
__device__ int   g_hist[BMAX];            // zeroed by scan each replay
__device__ int   g_cnt[BMAX];
__device__ int   g_binstart[BMAX];
__device__ int   g_cursor[BMAX];

// ---------------- 1. zW1[b,k,:] = z[b,k,:] @ W1  (B*K rows) ---------------
__global__ void zw1_kernel(const float* __restrict__ z,
                           const float* __restrict__ W1) {
    extern __shared__ __align__(16) float sm[];
    float* w1s = sm;              // LC*HC floats (64 KB)
    float* zs  = sm + LC * HC;    // 4*LC floats
    int tid = threadIdx.x;        // 256 threads

    for (int i = tid; i < (LC * HC) / 4; i += 256)
        ((float4*)w1s)[i] = ((const float4*)W1)[i];

    int row0 = blockIdx.x * 16;
    for (int g = 0; g < 4; g++) {
        int rbase = row0 + g * 4;
        __syncthreads();
        int rr = tid >> 6, ll = tid & 63;
        zs[rr * LC + ll] = z[(size_t)(rbase + rr) * LC + ll];
        __syncthreads();

        float a0 = 0.f, a1 = 0.f, a2 = 0.f, a3 = 0.f;
        #pragma unroll
        for (int l = 0; l < LC; l++) {
            float w = w1s[l * HC + tid];
            a0 += zs[0 * LC + l] * w;
            a1 += zs[1 * LC + l] * w;
            a2 += zs[2 * LC + l] * w;
            a3 += zs[3 * LC + l] * w;
        }
        g_zw1[(size_t)(rbase + 0) * HC + tid] = a0;
        g_zw1[(size_t)(rbase + 1) * HC + tid] = a1;
        g_zw1[(size_t)(rbase + 2) * HC + tid] = a2;
        g_zw1[(size_t)(rbase + 3) * HC + tid] = a3;
    }
}

// ---------------- 2. histogram of batch ids (int32) -----------------------
__global__ void hist_kernel(const int* __restrict__ batch, int n, int B) {
    __shared__ int sh[BMAX];
    int tid = threadIdx.x;
    sh[tid] = 0;
    __syncthreads();
    for (int i = blockIdx.x * blockDim.x + tid; i < n; i += gridDim.x * blockDim.x) {
        int b = batch[i];
        if (b >= 0 && b < B) atomicAdd(&sh[b], 1);
    }
    __syncthreads();
    if (sh[tid]) atomicAdd(&g_hist[tid], sh[tid]);
}

// ---------------- 3. exclusive scan; snapshot cnt; re-zero hist ------------
__global__ void scan_kernel() {
    __shared__ int tmp[BMAX];
    int tid = threadIdx.x;
    int v0 = g_hist[tid];
    g_cnt[tid]  = v0;
    g_hist[tid] = 0;               // idempotent across graph replays
    tmp[tid] = v0;
    __syncthreads();
    for (int d = 1; d < BMAX; d <<= 1) {
        int v = (tid >= d) ? tmp[tid - d] : 0;
        __syncthreads();
        tmp[tid] += v;
        __syncthreads();
    }
    int start = tmp[tid] - v0;     // exclusive
    g_binstart[tid] = start;
    g_cursor[tid]   = start;
}

// ---------------- 4. scatter node ids into bins ---------------------------
__global__ void scatter_kernel(const int* __restrict__ batch, int n, int B) {
    for (int i = blockIdx.x * blockDim.x + threadIdx.x; i < n;
         i += gridDim.x * blockDim.x) {
        int b = batch[i];
        if (b < 0 || b >= B) continue;
        int pos = atomicAdd(&g_cursor[b], 1);
        if (pos < NMAX) g_perm[pos] = i;
    }
}

// ---------------- 5. main fused kernel (f32x2 packed FMA) ------------------
// CTA = (graph b, chunk stride CPG). zW1[b] + W2(pre-paired) resident in SMEM.
// Warp tile: 4 nodes. h-stage pairs adjacent j; out-stage pairs even/odd-j
// partial sums in one u64 accumulator.
__global__ __launch_bounds__(256, 2)
void main_kernel(const float* __restrict__ s, const float* __restrict__ W2,
                 const float* __restrict__ b1, const float* __restrict__ b2,
                 float* __restrict__ out, int B) {
    extern __shared__ __align__(16) float sm[];
    float* zw1s = sm;                        // KC*HC   = 8192
    float* w2p  = zw1s + KC * HC;            // HC*OC   = 8192, layout [j/4][o][4]
    float* ss   = w2p + HC * OC;             // CHUNK*KC = 1024
    float* hsm  = ss + CHUNK * KC;           // 8*TNODES*HC = 8192
    float* b1s  = hsm + 8 * TNODES * HC;     // 256
    float* b2s  = b1s + HC;                  // 32
    int*   nids = (int*)(b2s + OC);          // CHUNK

    int tid = threadIdx.x;
    int b   = blockIdx.x % B;
    int c0  = blockIdx.x / B;
    int cnt = g_cnt[b];
    if (c0 * CHUNK >= cnt) return;           // uniform per CTA
    int start = g_binstart[b];

    // prologue: stage per-graph zW1, pre-paired W2, biases
    const float4* zw1g = (const float4*)(g_zw1 + (size_t)b * KC * HC);
    #pragma unroll
    for (int i = 0; i < 8; i++)
        ((float4*)zw1s)[tid + i * 256] = zw1g[tid + i * 256];
    #pragma unroll
    for (int e = 0; e < 8; e++) {
        int idx = e * 256 + tid;             // 0..2047
        int jp2 = idx >> 5, o = idx & 31, j = jp2 * 4;
        float4 v;
        v.x = W2[(j + 0) * OC + o];          // coalesced across lanes (o fast)
        v.y = W2[(j + 1) * OC + o];
        v.z = W2[(j + 2) * OC + o];
        v.w = W2[(j + 3) * OC + o];
        *(float4*)&w2p[idx * 4] = v;
    }
    b1s[tid] = b1[tid];
    if (tid < OC) b2s[tid] = b2[tid];

    int w = tid >> 5, lane = tid & 31;
    float* hw = hsm + w * TNODES * HC;       // this warp's h staging

    for (int c = c0; c * CHUNK < cnt; c += CPG) {
        int nbase = c * CHUNK;
        __syncthreads();                     // covers prologue + ss/nids reuse
        if (tid < CHUNK) {
            int idx = nbase + tid;
            nids[tid] = (idx < cnt) ? g_perm[start + idx] : -1;
        }
        __syncthreads();
        // stage s rows: CHUNK*KC/4 = 256 float4 -> one per thread
        {
            int i = tid >> 3, q = tid & 7;
            int nid = nids[i];
            float4 v = make_float4(0.f, 0.f, 0.f, 0.f);
            if (nid >= 0) v = ((const float4*)(s + (size_t)nid * KC))[q];
            ((float4*)(ss + i * KC))[q] = v;
        }
        __syncthreads();

        // ---- h-stage: h[t][j] = b1[j] + sum_k s[t,k]*zW1[k,j]
        // lane owns j = lane*8 .. lane*8+7 as 4 u64 pairs
        u64 ha[TNODES][4];
        {
            ulonglong2 p0 = *(ulonglong2*)&b1s[lane * 8];
            ulonglong2 p1 = *(ulonglong2*)&b1s[lane * 8 + 4];
            #pragma unroll
            for (int t = 0; t < TNODES; t++) {
                ha[t][0] = p0.x; ha[t][1] = p0.y;
                ha[t][2] = p1.x; ha[t][3] = p1.y;
            }
        }
        const float* ssw = ss + w * TNODES * KC;
        #pragma unroll 8
        for (int k = 0; k < KC; k++) {
            ulonglong2 wa = *(ulonglong2*)&zw1s[k * HC + lane * 8];
            ulonglong2 wb = *(ulonglong2*)&zw1s[k * HC + lane * 8 + 4];
            #pragma unroll
            for (int t = 0; t < TNODES; t++) {
                float sv = ssw[t * KC + k];          // broadcast
                u64 svp = pack2(sv, sv);
                ha[t][0] = fma2(svp, wa.x, ha[t][0]);
                ha[t][1] = fma2(svp, wa.y, ha[t][1]);
                ha[t][2] = fma2(svp, wb.x, ha[t][2]);
                ha[t][3] = fma2(svp, wb.y, ha[t][3]);
            }
        }
        // relu + stage h to SMEM (warp-local), layout [t][j]
        #pragma unroll
        for (int t = 0; t < TNODES; t++) {
            ulonglong2 o0, o1;
            float x, y;
            unpack2(ha[t][0], x, y); o0.x = pack2(fmaxf(x,0.f), fmaxf(y,0.f));
            unpack2(ha[t][1], x, y); o0.y = pack2(fmaxf(x,0.f), fmaxf(y,0.f));
            unpack2(ha[t][2], x, y); o1.x = pack2(fmaxf(x,0.f), fmaxf(y,0.f));
            unpack2(ha[t][3], x, y); o1.y = pack2(fmaxf(x,0.f), fmaxf(y,0.f));
            *(ulonglong2*)&hw[t * HC + lane * 8]     = o0;
            *(ulonglong2*)&hw[t * HC + lane * 8 + 4] = o1;
        }
        __syncwarp();

        // ---- out-stage: out[t][o=lane] = b2[o] + sum_j h[t][j]*W2[j][o]
        // acc[t]: u64 of (even-j partial, odd-j partial)
        u64 acc[TNODES];
        #pragma unroll
        for (int t = 0; t < TNODES; t++) acc[t] = 0ull;
        #pragma unroll 8
        for (int jp2 = 0; jp2 < HC / 4; jp2++) {
            ulonglong2 w2v = *(ulonglong2*)&w2p[jp2 * 128 + lane * 4]; // 4-phase
            #pragma unroll
            for (int t = 0; t < TNODES; t++) {
                ulonglong2 h2 = *(ulonglong2*)&hw[t * HC + jp2 * 4];   // broadcast
                acc[t] = fma2(h2.x, w2v.x, acc[t]);
                acc[t] = fma2(h2.y, w2v.y, acc[t]);
            }
        }
        #pragma unroll
        for (int t = 0; t < TNODES; t++) {
            int nid = nids[w * TNODES + t];
            if (nid >= 0) {
                float lo, hi;
                unpack2(acc[t], lo, hi);
                out[(size_t)nid * OC + lane] = lo + hi + b2s[lane];
            }
        }
        __syncwarp();   // hw safe to rewrite next chunk
    }
}

// ---------------- launch ---------------------------------------------------
extern "C" void kernel_launch(void* const* d_in, const int* in_sizes, int n_in,
                              void* d_out, int out_size) {
    const float* z     = (const float*)d_in[0];
    const float* s     = (const float*)d_in[1];
    const int*   batch = (const int*)d_in[2];   // JAX x64 disabled -> int32
    const float* W1    = (const float*)d_in[3];
    const float* b1    = (const float*)d_in[4];
    const float* W2    = (const float*)d_in[5];
    const float* b2    = (const float*)d_in[6];
    float*       out   = (float*)d_out;

    int n = in_sizes[2];
    int B = in_sizes[0] / (KC * LC);

    cudaFuncSetAttribute(zw1_kernel,
        cudaFuncAttributeMaxDynamicSharedMemorySize, ZW1_SMEM);
    cudaFuncSetAttribute(main_kernel,
        cudaFuncAttributeMaxDynamicSharedMemorySize, MAIN_SMEM);

    zw1_kernel<<<(B * KC) / 16, 256, ZW1_SMEM>>>(z, W1);
    hist_kernel<<<128, 256>>>(batch, n, B);
    scan_kernel<<<1, BMAX>>>();
    scatter_kernel<<<256, 256>>>(batch, n, B);
    main_kernel<<<B * CPG, 256, MAIN_SMEM>>>(s, W2, b1, b2, out, B);
}